// round 4
// baseline (speedup 1.0000x reference)
#include <cuda_runtime.h>

#define P  4
#define NN 100000
#define MM 50000
#define EE 400000
#define DD 128

// Scratch (__device__ globals; allocation at runtime is forbidden)
__device__ __align__(16) float g_y[P * NN * DD];      // 204.8 MB : x @ W_neigh
__device__ __align__(16) float g_self[P * MM * DD];   // 102.4 MB : x[:M] @ W_self + b
__device__ float g_inv[P * P * MM];                   // 1/max(deg,1) per (s,d)
__device__ int   g_deg[P * P * MM];                   // in-degree
__device__ int   g_off[P * P * MM];                   // CSR row offsets (per-pair local)
__device__ int   g_cur[P * P * MM];                   // fill cursors
__device__ int   g_csr[(size_t)P * P * EE];           // 25.6 MB : src ids grouped by dst

__constant__ int c_offd[12] = {1, 2, 3, 4, 6, 7, 8, 9, 11, 12, 13, 14};

// ---------------------------------------------------------------------------
// 0. Zero counters (kernel: graph memset nodes reject __device__ symbols)
// ---------------------------------------------------------------------------
__global__ void k_zero() {
    int i = blockIdx.x * blockDim.x + threadIdx.x;     // int4 index
    if (i < P * P * MM / 4) {
        ((int4*)g_deg)[i] = make_int4(0, 0, 0, 0);
        ((int4*)g_cur)[i] = make_int4(0, 0, 0, 0);
    }
}

// ---------------------------------------------------------------------------
// 1. Degree histogram (int atomics)  — edge indices are int32 (JAX w/o x64)
// ---------------------------------------------------------------------------
__global__ void k_count(const int* __restrict__ edst) {
    int pair = blockIdx.y;
    int e = blockIdx.x * blockDim.x + threadIdx.x;
    if (e >= EE) return;
    int dst = edst[(size_t)pair * EE + e];
    atomicAdd(&g_deg[pair * MM + dst], 1);
}

// ---------------------------------------------------------------------------
// 2. Per-pair exclusive scan of degrees -> CSR offsets; also 1/max(deg,1)
//    16 blocks (one per pair) x 1024 threads, chunked Hillis-Steele
// ---------------------------------------------------------------------------
__global__ __launch_bounds__(1024) void k_scan() {
    int pair = blockIdx.x;
    int tid = threadIdx.x;
    __shared__ int sh[1024];
    __shared__ int carry_s;
    if (tid == 0) carry_s = 0;
    __syncthreads();
    for (int base = 0; base < MM; base += 1024) {
        int idx = base + tid;
        int v = (idx < MM) ? g_deg[pair * MM + idx] : 0;
        sh[tid] = v;
        __syncthreads();
        #pragma unroll
        for (int off = 1; off < 1024; off <<= 1) {
            int t = (tid >= off) ? sh[tid - off] : 0;
            __syncthreads();
            sh[tid] += t;
            __syncthreads();
        }
        int carry = carry_s;
        if (idx < MM) {
            g_off[pair * MM + idx] = carry + sh[tid] - v;   // exclusive
            g_inv[pair * MM + idx] = 1.0f / fmaxf((float)v, 1.0f);
        }
        __syncthreads();
        if (tid == 0) carry_s = carry + sh[1023];
        __syncthreads();
    }
}

// ---------------------------------------------------------------------------
// 3. CSR fill: bin src ids by dst (int atomics on cursors)
// ---------------------------------------------------------------------------
__global__ void k_fill(const int* __restrict__ esrc,
                       const int* __restrict__ edst) {
    int pair = blockIdx.y;
    int e = blockIdx.x * blockDim.x + threadIdx.x;
    if (e >= EE) return;
    size_t eidx = (size_t)pair * EE + e;
    int src = esrc[eidx];
    int dst = edst[eidx];
    int mi = pair * MM + dst;
    int pos = atomicAdd(&g_cur[mi], 1);
    g_csr[(size_t)pair * EE + g_off[mi] + pos] = src;
}

// ---------------------------------------------------------------------------
// 4. Batched SGEMM: C[s] = A[s][:rows] @ W[s] (+ bias[s])
//    128x128 block, 8x8 microtile, BK=16, 256 threads
// ---------------------------------------------------------------------------
__global__ __launch_bounds__(256) void k_sgemm(
    const float* __restrict__ Aall, const float* __restrict__ Wall,
    const float* __restrict__ bias, float* __restrict__ Call,
    int rows, int strideA, int strideC)
{
    const int s = blockIdx.z;
    const float* A = Aall + (size_t)s * strideA;
    const float* W = Wall + s * DD * DD;
    float*       C = Call + (size_t)s * strideC;

    __shared__ float As[16][132];
    __shared__ float Ws[16][128];

    const int row0 = blockIdx.x * 128;
    const int tid = threadIdx.x;
    const int tx = tid & 15;
    const int ty = tid >> 4;

    float acc[8][8];
    #pragma unroll
    for (int i = 0; i < 8; i++)
        #pragma unroll
        for (int j = 0; j < 8; j++) acc[i][j] = 0.f;

    for (int k0 = 0; k0 < DD; k0 += 16) {
        #pragma unroll
        for (int it = 0; it < 2; it++) {
            int i = tid + it * 256;
            int r = i >> 2;
            int kq = i & 3;
            int gr = row0 + r;
            float4 v = make_float4(0.f, 0.f, 0.f, 0.f);
            if (gr < rows) v = *(const float4*)(A + (size_t)gr * DD + k0 + kq * 4);
            As[kq * 4 + 0][r] = v.x;
            As[kq * 4 + 1][r] = v.y;
            As[kq * 4 + 2][r] = v.z;
            As[kq * 4 + 3][r] = v.w;
        }
        #pragma unroll
        for (int it = 0; it < 2; it++) {
            int i = tid + it * 256;
            int kk = i >> 5;
            int jq = i & 31;
            *(float4*)&Ws[kk][jq * 4] = *(const float4*)(W + (k0 + kk) * DD + jq * 4);
        }
        __syncthreads();
        #pragma unroll
        for (int kk = 0; kk < 16; kk++) {
            float a[8], bb[8];
            *(float4*)&a[0]  = *(const float4*)&As[kk][ty * 8];
            *(float4*)&a[4]  = *(const float4*)&As[kk][ty * 8 + 4];
            *(float4*)&bb[0] = *(const float4*)&Ws[kk][tx * 8];
            *(float4*)&bb[4] = *(const float4*)&Ws[kk][tx * 8 + 4];
            #pragma unroll
            for (int i = 0; i < 8; i++)
                #pragma unroll
                for (int j = 0; j < 8; j++)
                    acc[i][j] += a[i] * bb[j];
        }
        __syncthreads();
    }

    float bv[8] = {0, 0, 0, 0, 0, 0, 0, 0};
    if (bias) {
        *(float4*)&bv[0] = *(const float4*)(bias + s * DD + tx * 8);
        *(float4*)&bv[4] = *(const float4*)(bias + s * DD + tx * 8 + 4);
    }
    #pragma unroll
    for (int i = 0; i < 8; i++) {
        int gr = row0 + ty * 8 + i;
        if (gr < rows) {
            float4 v0 = make_float4(acc[i][0] + bv[0], acc[i][1] + bv[1],
                                    acc[i][2] + bv[2], acc[i][3] + bv[3]);
            float4 v1 = make_float4(acc[i][4] + bv[4], acc[i][5] + bv[5],
                                    acc[i][6] + bv[6], acc[i][7] + bv[7]);
            *(float4*)(C + (size_t)gr * DD + tx * 8)     = v0;
            *(float4*)(C + (size_t)gr * DD + tx * 8 + 4) = v1;
        }
    }
}

// ---------------------------------------------------------------------------
// 5. Diagonal pairs (s==d): out[d][m] = self_d[m] + inv*sum(y_d[src])
//    One warp per row, register accumulation, PLAIN stores (initializes out)
// ---------------------------------------------------------------------------
__global__ __launch_bounds__(256) void k_diag(float* __restrict__ out) {
    const int d = blockIdx.y;
    const int pair = d * P + d;
    const int lane = threadIdx.x & 31;
    const int m = blockIdx.x * 8 + (threadIdx.x >> 5);
    const int mi = pair * MM + m;

    const int beg = g_off[mi];
    const int cnt = g_deg[mi];
    const float inv = g_inv[mi];
    const int* cs = g_csr + (size_t)pair * EE + beg;

    float4 acc = make_float4(0.f, 0.f, 0.f, 0.f);
    for (int e = 0; e < cnt; e++) {
        int src = cs[e];
        float4 v = *(const float4*)&g_y[((size_t)d * NN + src) * DD + lane * 4];
        acc.x += v.x; acc.y += v.y; acc.z += v.z; acc.w += v.w;
    }
    float4 sv = *(const float4*)&g_self[((size_t)d * MM + m) * DD + lane * 4];
    float4 r = make_float4(sv.x + acc.x * inv, sv.y + acc.y * inv,
                           sv.z + acc.z * inv, sv.w + acc.w * inv);
    *(float4*)&out[((size_t)d * MM + m) * DD + lane * 4] = r;
}

// ---------------------------------------------------------------------------
// 6. Off-diagonal pairs: out[d][merge[s,d][m]] += self_s[m] + inv*sum(y_s[src])
//    One warp per row; scalar float atomicAdd (merge indices may collide)
// ---------------------------------------------------------------------------
__global__ __launch_bounds__(256) void k_offdiag(const int* __restrict__ merge,
                                                 float* __restrict__ out) {
    const int pair = c_offd[blockIdx.y];
    const int s = pair >> 2, d = pair & 3;
    const int lane = threadIdx.x & 31;
    const int m = blockIdx.x * 8 + (threadIdx.x >> 5);
    const int mi = pair * MM + m;

    const int beg = g_off[mi];
    const int cnt = g_deg[mi];
    const float inv = g_inv[mi];
    const int* cs = g_csr + (size_t)pair * EE + beg;

    float4 acc = make_float4(0.f, 0.f, 0.f, 0.f);
    for (int e = 0; e < cnt; e++) {
        int src = cs[e];
        float4 v = *(const float4*)&g_y[((size_t)s * NN + src) * DD + lane * 4];
        acc.x += v.x; acc.y += v.y; acc.z += v.z; acc.w += v.w;
    }
    float4 sv = *(const float4*)&g_self[((size_t)s * MM + m) * DD + lane * 4];
    int t = merge[(size_t)pair * MM + m];

    float* p = out + ((size_t)d * MM + t) * DD + lane * 4;
    atomicAdd(p + 0, sv.x + acc.x * inv);
    atomicAdd(p + 1, sv.y + acc.y * inv);
    atomicAdd(p + 2, sv.z + acc.z * inv);
    atomicAdd(p + 3, sv.w + acc.w * inv);
}

// ---------------------------------------------------------------------------
extern "C" void kernel_launch(void* const* d_in, const int* in_sizes, int n_in,
                              void* d_out, int out_size) {
    const float* x      = (const float*)d_in[0];
    const float* Wself  = (const float*)d_in[1];
    const float* Wneigh = (const float*)d_in[2];
    const float* bias   = (const float*)d_in[3];
    const int*   esrc   = (const int*)d_in[4];    // int32 (JAX x64 disabled)
    const int*   edst   = (const int*)d_in[5];
    const int*   merge  = (const int*)d_in[6];
    float*       out    = (float*)d_out;

    void *self_p, *y_p;
    cudaGetSymbolAddress(&self_p, g_self);
    cudaGetSymbolAddress(&y_p, g_y);

    // CSR build
    k_zero<<<(P * P * MM / 4 + 255) / 256, 256>>>();
    k_count<<<dim3((EE + 255) / 256, P * P), 256>>>(edst);
    k_scan<<<P * P, 1024>>>();
    k_fill<<<dim3((EE + 255) / 256, P * P), 256>>>(esrc, edst);

    // GEMMs (hoisted): y = x @ W_neigh, self = x[:M] @ W_self + b
    k_sgemm<<<dim3((NN + 127) / 128, 1, P), 256>>>(
        x, Wneigh, nullptr, (float*)y_p, NN, NN * DD, NN * DD);
    k_sgemm<<<dim3((MM + 127) / 128, 1, P), 256>>>(
        x, Wself, bias, (float*)self_p, MM, NN * DD, MM * DD);

    // Aggregation + merge
    k_diag<<<dim3(MM / 8, P), 256>>>(out);
    k_offdiag<<<dim3(MM / 8, 12), 256>>>(merge, out);
}

// round 6
// speedup vs baseline: 1.4448x; 1.4448x over previous
#include <cuda_runtime.h>
#include <cuda_bf16.h>
#include <cstdint>

#define P  4
#define NN 100000
#define MM 50000
#define EE 400000
#define DD 128

#define NCHUNK 49                         // ceil(MM/1024)
#define NPAIR  16

// ---------------- device scratch (no runtime allocation allowed) ------------
__device__ __align__(16) float g_y[P * NN * DD];      // 204.8 MB : x @ W_neigh
__device__ __align__(16) float g_self[P * MM * DD];   // 102.4 MB : x[:M] @ W_self + b
__device__ float g_inv[NPAIR * MM];
__device__ int   g_deg[NPAIR * MM];
__device__ int   g_off[NPAIR * MM];
__device__ int   g_cur[NPAIR * MM];
__device__ int   g_csr[(size_t)NPAIR * EE];
__device__ int   g_bsum[NPAIR * NCHUNK];
__device__ int   g_boff[NPAIR * NCHUNK];
// W transposed to [n][k], split hi/lo bf16: per s, hi = 8192 u32, then lo
__device__ __align__(16) uint32_t g_wn[P * 16384];
__device__ __align__(16) uint32_t g_ws[P * 16384];

// ============================================================================
// CSR build
// ============================================================================
__global__ void k_zero() {
    int i = blockIdx.x * blockDim.x + threadIdx.x;
    if (i < NPAIR * MM / 4) {
        ((int4*)g_deg)[i] = make_int4(0, 0, 0, 0);
        ((int4*)g_cur)[i] = make_int4(0, 0, 0, 0);
    }
}

__global__ void k_count(const int* __restrict__ edst) {
    int pair = blockIdx.y;
    int e = blockIdx.x * blockDim.x + threadIdx.x;
    if (e >= EE) return;
    atomicAdd(&g_deg[pair * MM + edst[(size_t)pair * EE + e]], 1);
}

// scan phase 1: per-1024-chunk exclusive scan via warp shuffles
__global__ __launch_bounds__(1024) void k_scan1() {
    int bx = blockIdx.x;
    int pair = bx / NCHUNK, chunk = bx % NCHUNK;
    int tid = threadIdx.x, lane = tid & 31, warp = tid >> 5;
    int idx = chunk * 1024 + tid;
    int v = (idx < MM) ? g_deg[pair * MM + idx] : 0;
    int x = v;
    #pragma unroll
    for (int o = 1; o < 32; o <<= 1) {
        int t = __shfl_up_sync(0xFFFFFFFF, x, o);
        if (lane >= o) x += t;
    }
    __shared__ int ws[32];
    if (lane == 31) ws[warp] = x;
    __syncthreads();
    if (warp == 0) {
        int y = ws[lane];
        #pragma unroll
        for (int o = 1; o < 32; o <<= 1) {
            int t = __shfl_up_sync(0xFFFFFFFF, y, o);
            if (lane >= o) y += t;
        }
        ws[lane] = y;
    }
    __syncthreads();
    int incl = x + (warp > 0 ? ws[warp - 1] : 0);
    if (idx < MM) {
        g_off[pair * MM + idx] = incl - v;
        g_inv[pair * MM + idx] = 1.0f / fmaxf((float)v, 1.0f);
    }
    if (tid == 1023) g_bsum[bx] = incl;
}

// scan phase 2: per-pair exclusive scan of 49 chunk sums (1 block)
__global__ __launch_bounds__(1024) void k_scan2() {
    __shared__ int sm[NPAIR * NCHUNK];
    int tid = threadIdx.x;
    for (int i = tid; i < NPAIR * NCHUNK; i += 1024) sm[i] = g_bsum[i];
    __syncthreads();
    if (tid < NPAIR) {
        int run = 0;
        for (int j = 0; j < NCHUNK; j++) {
            int t = sm[tid * NCHUNK + j];
            sm[tid * NCHUNK + j] = run;
            run += t;
        }
    }
    __syncthreads();
    for (int i = tid; i < NPAIR * NCHUNK; i += 1024) g_boff[i] = sm[i];
}

// scan phase 3: add chunk offsets
__global__ __launch_bounds__(1024) void k_scan3() {
    int bx = blockIdx.x;
    int pair = bx / NCHUNK, chunk = bx % NCHUNK;
    int idx = chunk * 1024 + threadIdx.x;
    if (idx < MM) g_off[pair * MM + idx] += g_boff[bx];
}

__global__ void k_fill(const int* __restrict__ esrc, const int* __restrict__ edst) {
    int pair = blockIdx.y;
    int e = blockIdx.x * blockDim.x + threadIdx.x;
    if (e >= EE) return;
    size_t eidx = (size_t)pair * EE + e;
    int src = esrc[eidx];
    int mi = pair * MM + edst[eidx];
    int pos = atomicAdd(&g_cur[mi], 1);
    g_csr[(size_t)pair * EE + g_off[mi] + pos] = src;
}

// ============================================================================
// W precompute: B[n][k] = W[k][n], split hi/lo bf16
// layout per s: hi[n][k] as u32 pairs (n*64 + k/2), then lo at +8192
// ============================================================================
__global__ __launch_bounds__(256) void k_prepw(const float* __restrict__ Wn,
                                               const float* __restrict__ Ws) {
    int s = blockIdx.x;
    const float* W = (blockIdx.y == 0) ? (Wn + s * DD * DD) : (Ws + s * DD * DD);
    uint32_t* dst = (blockIdx.y == 0) ? (g_wn + s * 16384) : (g_ws + s * 16384);
    for (int it = threadIdx.x; it < 128 * 64; it += 256) {
        int n = it >> 6;          // output col = B row
        int k2 = it & 63;         // pair of k
        float f0 = W[(k2 * 2 + 0) * DD + n];
        float f1 = W[(k2 * 2 + 1) * DD + n];
        __nv_bfloat16 h0 = __float2bfloat16(f0), h1 = __float2bfloat16(f1);
        __nv_bfloat16 l0 = __float2bfloat16(f0 - __bfloat162float(h0));
        __nv_bfloat16 l1 = __float2bfloat16(f1 - __bfloat162float(h1));
        dst[n * 64 + k2] = ((uint32_t)__bfloat16_as_ushort(h1) << 16) | __bfloat16_as_ushort(h0);
        dst[8192 + n * 64 + k2] = ((uint32_t)__bfloat16_as_ushort(l1) << 16) | __bfloat16_as_ushort(l0);
    }
}

// ============================================================================
// mma.sync bf16 GEMM (hi/lo split, 3 passes): C = A @ W (+bias)
// tile 128x128x128, 256 threads (8 warps, 4m x 2n), warp tile 32x64
// ============================================================================
__device__ __forceinline__ void mma16816(float* c, const uint32_t* a, const uint32_t* b) {
    asm volatile(
        "mma.sync.aligned.m16n8k16.row.col.f32.bf16.bf16.f32 "
        "{%0,%1,%2,%3}, {%4,%5,%6,%7}, {%8,%9}, {%0,%1,%2,%3};"
        : "+f"(c[0]), "+f"(c[1]), "+f"(c[2]), "+f"(c[3])
        : "r"(a[0]), "r"(a[1]), "r"(a[2]), "r"(a[3]), "r"(b[0]), "r"(b[1]));
}

// smem byte offsets; rows padded to 136 bf16 (272 B) -> conflict-free frags
#define PITCH   272
#define SA_HI   0
#define SA_LO   34816
#define SB_HI   69632
#define SB_LO   104448
#define SM_BIAS 139264
#define SM_TOT  (139264 + 512)

__global__ __launch_bounds__(256, 1)
void k_gemm(const float* __restrict__ Aall, const uint32_t* __restrict__ Wall,
            const float* __restrict__ bias, float* __restrict__ Call,
            int rows, int strideA, int strideC)
{
    extern __shared__ char sm[];
    const int s = blockIdx.y;
    const int row0 = blockIdx.x * 128;
    const int tid = threadIdx.x;
    const int wid = tid >> 5, lane = tid & 31;

    // bias -> smem
    float* bias_sm = (float*)(sm + SM_BIAS);
    if (tid < 128) bias_sm[tid] = bias ? bias[s * DD + tid] : 0.0f;

    // B tiles: linear load of pre-split W, store at pitch 272
    {
        const uint2* srch = (const uint2*)(Wall + s * 16384);
        const uint2* srcl = (const uint2*)(Wall + s * 16384 + 8192);
        #pragma unroll
        for (int i = 0; i < 16; i++) {
            int idx = tid + i * 256;           // 4096 uint2 per buffer
            int n = idx >> 5, k4 = idx & 31;   // row, group of 4 k
            *(uint2*)(sm + SB_HI + n * PITCH + k4 * 8) = srch[idx];
            *(uint2*)(sm + SB_LO + n * PITCH + k4 * 8) = srcl[idx];
        }
    }

    // A tile: coalesced fp32 load, split hi/lo, store at pitch 272
    {
        const float* A = Aall + (size_t)s * strideA;
        #pragma unroll
        for (int i = 0; i < 16; i++) {
            int idx = tid + i * 256;           // 4096 float4
            int r = idx >> 5, c4 = idx & 31;
            int gr = row0 + r;
            float4 v = make_float4(0.f, 0.f, 0.f, 0.f);
            if (gr < rows) v = *(const float4*)(A + (size_t)gr * DD + c4 * 4);
            __nv_bfloat16 h0 = __float2bfloat16(v.x), h1 = __float2bfloat16(v.y);
            __nv_bfloat16 h2 = __float2bfloat16(v.z), h3 = __float2bfloat16(v.w);
            __nv_bfloat16 l0 = __float2bfloat16(v.x - __bfloat162float(h0));
            __nv_bfloat16 l1 = __float2bfloat16(v.y - __bfloat162float(h1));
            __nv_bfloat16 l2 = __float2bfloat16(v.z - __bfloat162float(h2));
            __nv_bfloat16 l3 = __float2bfloat16(v.w - __bfloat162float(h3));
            uint2 hi = make_uint2(((uint32_t)__bfloat16_as_ushort(h1) << 16) | __bfloat16_as_ushort(h0),
                                  ((uint32_t)__bfloat16_as_ushort(h3) << 16) | __bfloat16_as_ushort(h2));
            uint2 lo = make_uint2(((uint32_t)__bfloat16_as_ushort(l1) << 16) | __bfloat16_as_ushort(l0),
                                  ((uint32_t)__bfloat16_as_ushort(l3) << 16) | __bfloat16_as_ushort(l2));
            *(uint2*)(sm + SA_HI + r * PITCH + c4 * 8) = hi;
            *(uint2*)(sm + SA_LO + r * PITCH + c4 * 8) = lo;
        }
    }
    __syncthreads();

    const int wm = wid & 3;            // 4 m-groups of 32 rows
    const int wn = wid >> 2;           // 2 n-groups of 64 cols
    const int r_in = lane >> 2;        // 0..7
    const int cp = lane & 3;           // 0..3

    float c[2][8][4];
    #pragma unroll
    for (int mt = 0; mt < 2; mt++)
        #pragma unroll
        for (int nt = 0; nt < 8; nt++)
            #pragma unroll
            for (int j = 0; j < 4; j++) c[mt][nt][j] = 0.f;

    // 3 passes: Ah*Bh, Ah*Bl, Al*Bh
    const int aoff[3] = {SA_HI, SA_HI, SA_LO};
    const int boff[3] = {SB_HI, SB_LO, SB_HI};
    #pragma unroll
    for (int pass = 0; pass < 3; pass++) {
        const char* Ab = sm + aoff[pass];
        const char* Bb = sm + boff[pass];
        #pragma unroll
        for (int kk = 0; kk < 8; kk++) {
            const int kb = kk * 32 + cp * 4;   // byte offset of (k0 + cp*2) bf16
            uint32_t af[2][4], bf[8][2];
            #pragma unroll
            for (int mt = 0; mt < 2; mt++) {
                const char* ap = Ab + (wm * 32 + mt * 16 + r_in) * PITCH + kb;
                af[mt][0] = *(const uint32_t*)(ap);
                af[mt][1] = *(const uint32_t*)(ap + 8 * PITCH);
                af[mt][2] = *(const uint32_t*)(ap + 16);
                af[mt][3] = *(const uint32_t*)(ap + 8 * PITCH + 16);
            }
            #pragma unroll
            for (int nt = 0; nt < 8; nt++) {
                const char* bp = Bb + (wn * 64 + nt * 8 + r_in) * PITCH + kb;
                bf[nt][0] = *(const uint32_t*)(bp);
                bf[nt][1] = *(const uint32_t*)(bp + 16);
            }
            #pragma unroll
            for (int mt = 0; mt < 2; mt++)
                #pragma unroll
                for (int nt = 0; nt < 8; nt++)
                    mma16816(c[mt][nt], af[mt], bf[nt]);
        }
    }

    // epilogue
    float* C = Call + (size_t)s * strideC;
    #pragma unroll
    for (int mt = 0; mt < 2; mt++) {
        int gr0 = row0 + wm * 32 + mt * 16 + r_in;
        #pragma unroll
        for (int nt = 0; nt < 8; nt++) {
            int col = wn * 64 + nt * 8 + cp * 2;
            float b0 = bias_sm[col], b1 = bias_sm[col + 1];
            if (gr0 < rows)
                *(float2*)(C + (size_t)gr0 * DD + col) =
                    make_float2(c[mt][nt][0] + b0, c[mt][nt][1] + b1);
            if (gr0 + 8 < rows)
                *(float2*)(C + (size_t)(gr0 + 8) * DD + col) =
                    make_float2(c[mt][nt][2] + b0, c[mt][nt][3] + b1);
        }
    }
}

// ============================================================================
// out init + fused aggregation
// ============================================================================
__global__ void k_init(float* __restrict__ out) {
    size_t i = (size_t)blockIdx.x * blockDim.x + threadIdx.x;
    ((float4*)out)[i] = ((const float4*)g_self)[i];
}

// All 16 pairs, block order s-major so y_s stays L2-resident per group.
#define BPP (MM / 8)
__global__ __launch_bounds__(256) void k_agg(const int* __restrict__ merge,
                                             float* __restrict__ out) {
    const int pair = blockIdx.x / BPP;                 // s-major: pair = s*4+d
    const int s = pair >> 2, d = pair & 3;
    const int lane = threadIdx.x & 31;
    const int m = (blockIdx.x % BPP) * 8 + (threadIdx.x >> 5);
    const int mi = pair * MM + m;

    const int beg = g_off[mi];
    const int cnt = g_deg[mi];
    const float inv = g_inv[mi];
    const int* cs = g_csr + (size_t)pair * EE + beg;
    const float* ys = g_y + (size_t)s * NN * DD;

    float4 acc = make_float4(0.f, 0.f, 0.f, 0.f);
    for (int e = 0; e < cnt; e++) {
        int src = cs[e];
        float4 v = *(const float4*)(ys + (size_t)src * DD + lane * 4);
        acc.x += v.x; acc.y += v.y; acc.z += v.z; acc.w += v.w;
    }
    acc.x *= inv; acc.y *= inv; acc.z *= inv; acc.w *= inv;

    int t = m;
    if (s != d) {
        t = merge[(size_t)pair * MM + m];
        float4 sv = *(const float4*)&g_self[((size_t)s * MM + m) * DD + lane * 4];
        acc.x += sv.x; acc.y += sv.y; acc.z += sv.z; acc.w += sv.w;
    }
    float* p = out + ((size_t)d * MM + t) * DD + lane * 4;
    atomicAdd(p + 0, acc.x);
    atomicAdd(p + 1, acc.y);
    atomicAdd(p + 2, acc.z);
    atomicAdd(p + 3, acc.w);
}

// ============================================================================
extern "C" void kernel_launch(void* const* d_in, const int* in_sizes, int n_in,
                              void* d_out, int out_size) {
    const float* x      = (const float*)d_in[0];
    const float* Wself  = (const float*)d_in[1];
    const float* Wneigh = (const float*)d_in[2];
    const float* bias   = (const float*)d_in[3];
    const int*   esrc   = (const int*)d_in[4];
    const int*   edst   = (const int*)d_in[5];
    const int*   merge  = (const int*)d_in[6];
    float*       out    = (float*)d_out;

    void *y_p, *self_p, *wn_p, *ws_p;
    cudaGetSymbolAddress(&y_p, g_y);
    cudaGetSymbolAddress(&self_p, g_self);
    cudaGetSymbolAddress(&wn_p, g_wn);
    cudaGetSymbolAddress(&ws_p, g_ws);

    cudaFuncSetAttribute(k_gemm, cudaFuncAttributeMaxDynamicSharedMemorySize, SM_TOT);

    // CSR build
    k_zero<<<(NPAIR * MM / 4 + 255) / 256, 256>>>();
    k_count<<<dim3((EE + 255) / 256, NPAIR), 256>>>(edst);
    k_scan1<<<NPAIR * NCHUNK, 1024>>>();
    k_scan2<<<1, 1024>>>();
    k_scan3<<<NPAIR * NCHUNK, 1024>>>();
    k_fill<<<dim3((EE + 255) / 256, NPAIR), 256>>>(esrc, edst);

    // W precompute (transposed, hi/lo bf16)
    k_prepw<<<dim3(P, 2), 256>>>(Wneigh, Wself);

    // tensor-core GEMMs (mma.sync)
    k_gemm<<<dim3((NN + 127) / 128, P), 256, SM_TOT>>>(
        x, (const uint32_t*)wn_p, nullptr, (float*)y_p, NN, NN * DD, NN * DD);
    k_gemm<<<dim3((MM + 127) / 128, P), 256, SM_TOT>>>(
        x, (const uint32_t*)ws_p, bias, (float*)self_p, MM, NN * DD, MM * DD);

    // out = self (diag), then fused all-pair aggregation
    k_init<<<(P * MM * DD / 4) / 256, 256>>>(out);
    k_agg<<<NPAIR * BPP, 256>>>(merge, out);
}

// round 7
// speedup vs baseline: 1.5231x; 1.0542x over previous
#include <cuda_runtime.h>
#include <cuda_bf16.h>
#include <cstdint>

#define P  4
#define NN 100000
#define MM 50000
#define EE 400000
#define DD 128

#define NCHUNK 49                         // ceil(MM/1024)
#define NPAIR  16

// ---------------- device scratch (no runtime allocation allowed) ------------
__device__ __align__(16) uint32_t g_ybf[(size_t)P * NN * 64];  // 102.4 MB : bf16x2 y = x @ W_neigh
__device__ __align__(16) float g_self[P * MM * DD];            // 102.4 MB : x[:M] @ W_self + b
__device__ float g_inv[NPAIR * MM];
__device__ int   g_deg[NPAIR * MM];
__device__ int   g_off[NPAIR * MM];
__device__ int   g_cur[NPAIR * MM];
__device__ int   g_csr[(size_t)NPAIR * EE];
__device__ int   g_bsum[NPAIR * NCHUNK];
__device__ int   g_boff[NPAIR * NCHUNK];
// W transposed to [n][k], split hi/lo bf16: per s, hi = 8192 u32, then lo
__device__ __align__(16) uint32_t g_wn[P * 16384];
__device__ __align__(16) uint32_t g_ws[P * 16384];

// off-diagonal pairs (pair = s*4 + d), ascending = s-major order
__constant__ int c_offd[12] = {1, 2, 3, 4, 6, 7, 8, 9, 11, 12, 13, 14};

// ============================================================================
// CSR build
// ============================================================================
__global__ void k_zero() {
    int i = blockIdx.x * blockDim.x + threadIdx.x;
    if (i < NPAIR * MM / 4) {
        ((int4*)g_deg)[i] = make_int4(0, 0, 0, 0);
        ((int4*)g_cur)[i] = make_int4(0, 0, 0, 0);
    }
}

__global__ void k_count(const int* __restrict__ edst) {
    int pair = blockIdx.y;
    int e = blockIdx.x * blockDim.x + threadIdx.x;
    if (e >= EE) return;
    atomicAdd(&g_deg[pair * MM + edst[(size_t)pair * EE + e]], 1);
}

__global__ __launch_bounds__(1024) void k_scan1() {
    int bx = blockIdx.x;
    int pair = bx / NCHUNK, chunk = bx % NCHUNK;
    int tid = threadIdx.x, lane = tid & 31, warp = tid >> 5;
    int idx = chunk * 1024 + tid;
    int v = (idx < MM) ? g_deg[pair * MM + idx] : 0;
    int x = v;
    #pragma unroll
    for (int o = 1; o < 32; o <<= 1) {
        int t = __shfl_up_sync(0xFFFFFFFF, x, o);
        if (lane >= o) x += t;
    }
    __shared__ int ws[32];
    if (lane == 31) ws[warp] = x;
    __syncthreads();
    if (warp == 0) {
        int y = ws[lane];
        #pragma unroll
        for (int o = 1; o < 32; o <<= 1) {
            int t = __shfl_up_sync(0xFFFFFFFF, y, o);
            if (lane >= o) y += t;
        }
        ws[lane] = y;
    }
    __syncthreads();
    int incl = x + (warp > 0 ? ws[warp - 1] : 0);
    if (idx < MM) {
        g_off[pair * MM + idx] = incl - v;
        g_inv[pair * MM + idx] = 1.0f / fmaxf((float)v, 1.0f);
    }
    if (tid == 1023) g_bsum[bx] = incl;
}

__global__ __launch_bounds__(1024) void k_scan2() {
    __shared__ int sm[NPAIR * NCHUNK];
    int tid = threadIdx.x;
    for (int i = tid; i < NPAIR * NCHUNK; i += 1024) sm[i] = g_bsum[i];
    __syncthreads();
    if (tid < NPAIR) {
        int run = 0;
        for (int j = 0; j < NCHUNK; j++) {
            int t = sm[tid * NCHUNK + j];
            sm[tid * NCHUNK + j] = run;
            run += t;
        }
    }
    __syncthreads();
    for (int i = tid; i < NPAIR * NCHUNK; i += 1024) g_boff[i] = sm[i];
}

__global__ __launch_bounds__(1024) void k_scan3() {
    int bx = blockIdx.x;
    int pair = bx / NCHUNK, chunk = bx % NCHUNK;
    int idx = chunk * 1024 + threadIdx.x;
    if (idx < MM) g_off[pair * MM + idx] += g_boff[bx];
}

__global__ void k_fill(const int* __restrict__ esrc, const int* __restrict__ edst) {
    int pair = blockIdx.y;
    int e = blockIdx.x * blockDim.x + threadIdx.x;
    if (e >= EE) return;
    size_t eidx = (size_t)pair * EE + e;
    int src = esrc[eidx];
    int mi = pair * MM + edst[eidx];
    int pos = atomicAdd(&g_cur[mi], 1);
    g_csr[(size_t)pair * EE + g_off[mi] + pos] = src;
}

// ============================================================================
// W precompute: B[n][k] = W[k][n], split hi/lo bf16
// ============================================================================
__global__ __launch_bounds__(256) void k_prepw(const float* __restrict__ Wn,
                                               const float* __restrict__ Ws) {
    int s = blockIdx.x;
    const float* W = (blockIdx.y == 0) ? (Wn + s * DD * DD) : (Ws + s * DD * DD);
    uint32_t* dst = (blockIdx.y == 0) ? (g_wn + s * 16384) : (g_ws + s * 16384);
    for (int it = threadIdx.x; it < 128 * 64; it += 256) {
        int n = it >> 6;
        int k2 = it & 63;
        float f0 = W[(k2 * 2 + 0) * DD + n];
        float f1 = W[(k2 * 2 + 1) * DD + n];
        __nv_bfloat16 h0 = __float2bfloat16(f0), h1 = __float2bfloat16(f1);
        __nv_bfloat16 l0 = __float2bfloat16(f0 - __bfloat162float(h0));
        __nv_bfloat16 l1 = __float2bfloat16(f1 - __bfloat162float(h1));
        dst[n * 64 + k2] = ((uint32_t)__bfloat16_as_ushort(h1) << 16) | __bfloat16_as_ushort(h0);
        dst[8192 + n * 64 + k2] = ((uint32_t)__bfloat16_as_ushort(l1) << 16) | __bfloat16_as_ushort(l0);
    }
}

// ============================================================================
// mma.sync bf16 GEMM (hi/lo split, 3 passes): C = A @ W (+bias)
// tile 128x128x128, 256 threads (8 warps, 4m x 2n), warp tile 32x64
// Cf (fp32 out) or Cbf (bf16x2 out) — exactly one non-null.
// ============================================================================
__device__ __forceinline__ void mma16816(float* c, const uint32_t* a, const uint32_t* b) {
    asm volatile(
        "mma.sync.aligned.m16n8k16.row.col.f32.bf16.bf16.f32 "
        "{%0,%1,%2,%3}, {%4,%5,%6,%7}, {%8,%9}, {%0,%1,%2,%3};"
        : "+f"(c[0]), "+f"(c[1]), "+f"(c[2]), "+f"(c[3])
        : "r"(a[0]), "r"(a[1]), "r"(a[2]), "r"(a[3]), "r"(b[0]), "r"(b[1]));
}

#define PITCH   272
#define SA_HI   0
#define SA_LO   34816
#define SB_HI   69632
#define SB_LO   104448
#define SM_BIAS 139264
#define SM_TOT  (139264 + 512)

__global__ __launch_bounds__(256, 1)
void k_gemm(const float* __restrict__ Aall, const uint32_t* __restrict__ Wall,
            const float* __restrict__ bias, float* __restrict__ Cf,
            uint32_t* __restrict__ Cbf, int rows, int strideA, int strideC)
{
    extern __shared__ char sm[];
    const int s = blockIdx.y;
    const int row0 = blockIdx.x * 128;
    const int tid = threadIdx.x;
    const int wid = tid >> 5, lane = tid & 31;

    float* bias_sm = (float*)(sm + SM_BIAS);
    if (tid < 128) bias_sm[tid] = bias ? bias[s * DD + tid] : 0.0f;

    {
        const uint2* srch = (const uint2*)(Wall + s * 16384);
        const uint2* srcl = (const uint2*)(Wall + s * 16384 + 8192);
        #pragma unroll
        for (int i = 0; i < 16; i++) {
            int idx = tid + i * 256;
            int n = idx >> 5, k4 = idx & 31;
            *(uint2*)(sm + SB_HI + n * PITCH + k4 * 8) = srch[idx];
            *(uint2*)(sm + SB_LO + n * PITCH + k4 * 8) = srcl[idx];
        }
    }
    {
        const float* A = Aall + (size_t)s * strideA;
        #pragma unroll
        for (int i = 0; i < 16; i++) {
            int idx = tid + i * 256;
            int r = idx >> 5, c4 = idx & 31;
            int gr = row0 + r;
            float4 v = make_float4(0.f, 0.f, 0.f, 0.f);
            if (gr < rows) v = *(const float4*)(A + (size_t)gr * DD + c4 * 4);
            __nv_bfloat16 h0 = __float2bfloat16(v.x), h1 = __float2bfloat16(v.y);
            __nv_bfloat16 h2 = __float2bfloat16(v.z), h3 = __float2bfloat16(v.w);
            __nv_bfloat16 l0 = __float2bfloat16(v.x - __bfloat162float(h0));
            __nv_bfloat16 l1 = __float2bfloat16(v.y - __bfloat162float(h1));
            __nv_bfloat16 l2 = __float2bfloat16(v.z - __bfloat162float(h2));
            __nv_bfloat16 l3 = __float2bfloat16(v.w - __bfloat162float(h3));
            uint2 hi = make_uint2(((uint32_t)__bfloat16_as_ushort(h1) << 16) | __bfloat16_as_ushort(h0),
                                  ((uint32_t)__bfloat16_as_ushort(h3) << 16) | __bfloat16_as_ushort(h2));
            uint2 lo = make_uint2(((uint32_t)__bfloat16_as_ushort(l1) << 16) | __bfloat16_as_ushort(l0),
                                  ((uint32_t)__bfloat16_as_ushort(l3) << 16) | __bfloat16_as_ushort(l2));
            *(uint2*)(sm + SA_HI + r * PITCH + c4 * 8) = hi;
            *(uint2*)(sm + SA_LO + r * PITCH + c4 * 8) = lo;
        }
    }
    __syncthreads();

    const int wm = wid & 3;
    const int wn = wid >> 2;
    const int r_in = lane >> 2;
    const int cp = lane & 3;

    float c[2][8][4];
    #pragma unroll
    for (int mt = 0; mt < 2; mt++)
        #pragma unroll
        for (int nt = 0; nt < 8; nt++)
            #pragma unroll
            for (int j = 0; j < 4; j++) c[mt][nt][j] = 0.f;

    const int aoff[3] = {SA_HI, SA_HI, SA_LO};
    const int boff[3] = {SB_HI, SB_LO, SB_HI};
    #pragma unroll
    for (int pass = 0; pass < 3; pass++) {
        const char* Ab = sm + aoff[pass];
        const char* Bb = sm + boff[pass];
        #pragma unroll
        for (int kk = 0; kk < 8; kk++) {
            const int kb = kk * 32 + cp * 4;
            uint32_t af[2][4], bf[8][2];
            #pragma unroll
            for (int mt = 0; mt < 2; mt++) {
                const char* ap = Ab + (wm * 32 + mt * 16 + r_in) * PITCH + kb;
                af[mt][0] = *(const uint32_t*)(ap);
                af[mt][1] = *(const uint32_t*)(ap + 8 * PITCH);
                af[mt][2] = *(const uint32_t*)(ap + 16);
                af[mt][3] = *(const uint32_t*)(ap + 8 * PITCH + 16);
            }
            #pragma unroll
            for (int nt = 0; nt < 8; nt++) {
                const char* bp = Bb + (wn * 64 + nt * 8 + r_in) * PITCH + kb;
                bf[nt][0] = *(const uint32_t*)(bp);
                bf[nt][1] = *(const uint32_t*)(bp + 16);
            }
            #pragma unroll
            for (int mt = 0; mt < 2; mt++)
                #pragma unroll
                for (int nt = 0; nt < 8; nt++)
                    mma16816(c[mt][nt], af[mt], bf[nt]);
        }
    }

    if (Cbf) {   // bf16x2 output (y path, no bias)
        #pragma unroll
        for (int mt = 0; mt < 2; mt++) {
            int gr0 = row0 + wm * 32 + mt * 16 + r_in;
            #pragma unroll
            for (int nt = 0; nt < 8; nt++) {
                int col = wn * 64 + nt * 8 + cp * 2;
                if (gr0 < rows) {
                    __nv_bfloat162 b = __float22bfloat162_rn(make_float2(c[mt][nt][0], c[mt][nt][1]));
                    Cbf[(size_t)(s * NN + gr0) * 64 + (col >> 1)] = *(uint32_t*)&b;
                }
                if (gr0 + 8 < rows) {
                    __nv_bfloat162 b = __float22bfloat162_rn(make_float2(c[mt][nt][2], c[mt][nt][3]));
                    Cbf[(size_t)(s * NN + gr0 + 8) * 64 + (col >> 1)] = *(uint32_t*)&b;
                }
            }
        }
    } else {     // fp32 output (+bias)
        float* C = Cf + (size_t)s * strideC;
        #pragma unroll
        for (int mt = 0; mt < 2; mt++) {
            int gr0 = row0 + wm * 32 + mt * 16 + r_in;
            #pragma unroll
            for (int nt = 0; nt < 8; nt++) {
                int col = wn * 64 + nt * 8 + cp * 2;
                float b0 = bias_sm[col], b1 = bias_sm[col + 1];
                if (gr0 < rows)
                    *(float2*)(C + (size_t)gr0 * DD + col) =
                        make_float2(c[mt][nt][0] + b0, c[mt][nt][1] + b1);
                if (gr0 + 8 < rows)
                    *(float2*)(C + (size_t)(gr0 + 8) * DD + col) =
                        make_float2(c[mt][nt][2] + b0, c[mt][nt][3] + b1);
            }
        }
    }
}

// ============================================================================
// Aggregation. Diagonal: plain stores (also initializes out). Off-diag: atomics.
// Warp per (pair, m); lane covers 4 cols -> uint2 of bf16x2 per edge.
// ============================================================================
__device__ __forceinline__ float4 gather_row(const uint32_t* ys, int src, int lane) {
    uint2 v = *(const uint2*)(ys + (size_t)src * 64 + lane * 2);
    __nv_bfloat162 b0 = *(__nv_bfloat162*)&v.x;
    __nv_bfloat162 b1 = *(__nv_bfloat162*)&v.y;
    float2 f0 = __bfloat1622float2(b0);
    float2 f1 = __bfloat1622float2(b1);
    return make_float4(f0.x, f0.y, f1.x, f1.y);
}

#define BPP (MM / 8)   // 6250 blocks/pair, 8 warps/block

__global__ __launch_bounds__(256) void k_diag(float* __restrict__ out) {
    const int d = blockIdx.y;
    const int pair = d * 5;                     // s==d
    const int lane = threadIdx.x & 31;
    const int m = blockIdx.x * 8 + (threadIdx.x >> 5);
    const int mi = pair * MM + m;

    const int beg = g_off[mi];
    const int cnt = g_deg[mi];
    const float inv = g_inv[mi];
    const int* cs = g_csr + (size_t)pair * EE + beg;
    const uint32_t* ys = g_ybf + (size_t)d * NN * 64;

    float4 acc = make_float4(0.f, 0.f, 0.f, 0.f);
    for (int e = 0; e < cnt; e++) {
        float4 v = gather_row(ys, cs[e], lane);
        acc.x += v.x; acc.y += v.y; acc.z += v.z; acc.w += v.w;
    }
    float4 sv = *(const float4*)&g_self[((size_t)d * MM + m) * DD + lane * 4];
    *(float4*)&out[((size_t)d * MM + m) * DD + lane * 4] =
        make_float4(sv.x + acc.x * inv, sv.y + acc.y * inv,
                    sv.z + acc.z * inv, sv.w + acc.w * inv);
}

__global__ __launch_bounds__(256) void k_offdiag(const int* __restrict__ merge,
                                                 float* __restrict__ out) {
    const int pair = c_offd[blockIdx.x / BPP];  // s-major ordering
    const int s = pair >> 2, d = pair & 3;
    const int lane = threadIdx.x & 31;
    const int m = (blockIdx.x % BPP) * 8 + (threadIdx.x >> 5);
    const int mi = pair * MM + m;

    const int beg = g_off[mi];
    const int cnt = g_deg[mi];
    const float inv = g_inv[mi];
    const int* cs = g_csr + (size_t)pair * EE + beg;
    const uint32_t* ys = g_ybf + (size_t)s * NN * 64;

    float4 acc = make_float4(0.f, 0.f, 0.f, 0.f);
    for (int e = 0; e < cnt; e++) {
        float4 v = gather_row(ys, cs[e], lane);
        acc.x += v.x; acc.y += v.y; acc.z += v.z; acc.w += v.w;
    }
    float4 sv = *(const float4*)&g_self[((size_t)s * MM + m) * DD + lane * 4];
    int t = merge[(size_t)pair * MM + m];

    float* p = out + ((size_t)d * MM + t) * DD + lane * 4;
    atomicAdd(p + 0, sv.x + acc.x * inv);
    atomicAdd(p + 1, sv.y + acc.y * inv);
    atomicAdd(p + 2, sv.z + acc.z * inv);
    atomicAdd(p + 3, sv.w + acc.w * inv);
}

// ============================================================================
extern "C" void kernel_launch(void* const* d_in, const int* in_sizes, int n_in,
                              void* d_out, int out_size) {
    const float* x      = (const float*)d_in[0];
    const float* Wself  = (const float*)d_in[1];
    const float* Wneigh = (const float*)d_in[2];
    const float* bias   = (const float*)d_in[3];
    const int*   esrc   = (const int*)d_in[4];
    const int*   edst   = (const int*)d_in[5];
    const int*   merge  = (const int*)d_in[6];
    float*       out    = (float*)d_out;

    void *y_p, *self_p, *wn_p, *ws_p;
    cudaGetSymbolAddress(&y_p, g_ybf);
    cudaGetSymbolAddress(&self_p, g_self);
    cudaGetSymbolAddress(&wn_p, g_wn);
    cudaGetSymbolAddress(&ws_p, g_ws);

    cudaFuncSetAttribute(k_gemm, cudaFuncAttributeMaxDynamicSharedMemorySize, SM_TOT);

    // CSR build
    k_zero<<<(NPAIR * MM / 4 + 255) / 256, 256>>>();
    k_count<<<dim3((EE + 255) / 256, NPAIR), 256>>>(edst);
    k_scan1<<<NPAIR * NCHUNK, 1024>>>();
    k_scan2<<<1, 1024>>>();
    k_scan3<<<NPAIR * NCHUNK, 1024>>>();
    k_fill<<<dim3((EE + 255) / 256, NPAIR), 256>>>(esrc, edst);

    // W precompute (transposed, hi/lo bf16)
    k_prepw<<<dim3(P, 2), 256>>>(Wneigh, Wself);

    // GEMMs: y (bf16x2 out), self (fp32 out, +bias)
    k_gemm<<<dim3((NN + 127) / 128, P), 256, SM_TOT>>>(
        x, (const uint32_t*)wn_p, nullptr, nullptr, (uint32_t*)y_p, NN, NN * DD, 0);
    k_gemm<<<dim3((MM + 127) / 128, P), 256, SM_TOT>>>(
        x, (const uint32_t*)ws_p, bias, (float*)self_p, nullptr, MM, NN * DD, MM * DD);

    // Aggregation: diag (plain stores, initializes out), then off-diag (atomics)
    k_diag<<<dim3(MM / 8, P), 256>>>(out);
    k_offdiag<<<12 * BPP, 256>>>(merge, out);
}